// round 11
// baseline (speedup 1.0000x reference)
#include <cuda_runtime.h>
#include <cuda_fp16.h>
#include <cstdint>

#define LN_EPS 1e-5f

// ============================ PTX helpers ============================
__device__ __forceinline__ uint32_t smem_u32(const void* p) {
    uint32_t a;
    asm("{ .reg .u64 t; cvta.to.shared.u64 t, %1; cvt.u32.u64 %0, t; }"
        : "=r"(a) : "l"(p));
    return a;
}

__device__ __forceinline__ uint32_t swz(uint32_t off) {
    return off ^ ((off >> 3) & 0x70);   // SW128 XOR swizzle
}

#define LDSM4(r, addr)                                                        \
    asm volatile(                                                             \
        "ldmatrix.sync.aligned.m8n8.x4.shared.b16 {%0,%1,%2,%3}, [%4];"       \
        : "=r"((r)[0]), "=r"((r)[1]), "=r"((r)[2]), "=r"((r)[3])              \
        : "r"(addr))

#define MMAF16(d, a, b0, b1)                                                  \
    asm volatile(                                                             \
        "mma.sync.aligned.m16n8k16.row.col.f32.f16.f16.f32 "                  \
        "{%0,%1,%2,%3}, {%4,%5,%6,%7}, {%8,%9}, {%0,%1,%2,%3};"               \
        : "+f"((d)[0]), "+f"((d)[1]), "+f"((d)[2]), "+f"((d)[3])              \
        : "r"((a)[0]), "r"((a)[1]), "r"((a)[2]), "r"((a)[3]),                 \
          "r"(b0), "r"(b1))

#define CP_ASYNC16(dst, src)                                                  \
    asm volatile("cp.async.cg.shared.global [%0], [%1], 16;"                  \
                 :: "r"(dst), "l"(src))
#define CP_ASYNC_COMMIT() asm volatile("cp.async.commit_group;" ::: "memory")
#define CP_ASYNC_WAIT1()  asm volatile("cp.async.wait_group 1;" ::: "memory")
#define CP_ASYNC_WAIT0()  asm volatile("cp.async.wait_group 0;" ::: "memory")

// ============================ geometry ============================
constexpr int TM    = 128;
constexpr int KCH   = 64;
constexpr int ATILE = TM * 128;          // 16384 B per A limb tile

__host__ __device__ constexpr int npass_of(int dout) {
    return dout > 256 ? 256 : dout;
}
__host__ __device__ constexpr int bufb_of(int dout) {
    return 2 * ATILE + 2 * npass_of(dout) * 128;
}
__host__ __device__ constexpr int smem_of(int dout) {
    return 2 * bufb_of(dout) + 7168;
}

// ============================ scratch ============================
__device__ __align__(256) float  g_h[98304ull * 512];
__device__ __align__(256) __half g_a0[98304ull * 768];
__device__ __align__(256) __half g_a1[98304ull * 768];
__device__ __align__(256) __half g_c0[98304ull * 512];
__device__ __align__(256) __half g_c1[98304ull * 512];
__device__ __align__(256) __half g_p0[98304ull * 128];
__device__ __align__(256) __half g_p1[98304ull * 128];
__device__ __align__(256) __half g_w0[724992];
__device__ __align__(256) __half g_w1[724992];
__device__ float g_psum[64 * 32];
__device__ float g_pcnt[64];

// ============================ 2-way fp16 split ============================
__device__ __forceinline__ void split2(float a, __half& h0, __half& h1) {
    h0 = __float2half_rn(a);
    h1 = __float2half_rn(a - __half2float(h0));
}
__device__ __forceinline__ uint32_t pack2(__half a, __half b) {
    return ((uint32_t)__half_as_ushort(b) << 16) | (uint32_t)__half_as_ushort(a);
}

// ============================ W prep (single launch) ============================
__global__ void split_w_all(const float* __restrict__ W1,
                            const float* __restrict__ W2,
                            const float* __restrict__ W3,
                            const float* __restrict__ W4) {
    int i = blockIdx.x * 256 + threadIdx.x;
    if (i >= 724992) return;
    float v;
    if (i < 393216) v = W1[i];
    else if (i < 655360) v = W2[i - 393216];
    else if (i < 720896) v = W3[i - 655360];
    else v = W4[i - 720896];
    __half h0, h1;
    split2(v, h0, h1);
    g_w0[i] = h0;
    g_w1[i] = h1;
}

// ============================ input convert ============================
__global__ __launch_bounds__(256) void convert_in(
    const float* __restrict__ x, __half* __restrict__ o0,
    __half* __restrict__ o1, int total8) {
    int i = blockIdx.x * 256 + threadIdx.x;
    if (i >= total8) return;
    int r = i / 96;                       // din = 768 -> 96 quads
    int q = i - r * 96;
    const float* src = x + (int64_t)r * 768 + q * 8;
    float4 v0 = *(const float4*)src;
    float4 v1 = *(const float4*)(src + 4);
    float xx[8] = {v0.x, v0.y, v0.z, v0.w, v1.x, v1.y, v1.z, v1.w};
    __half h0[8], h1[8];
#pragma unroll
    for (int j = 0; j < 8; j++) split2(xx[j], h0[j], h1[j]);
    int64_t o = (int64_t)r * 768 + q * 8;
    *(uint4*)(o0 + o) = make_uint4(pack2(h0[0], h0[1]), pack2(h0[2], h0[3]),
                                   pack2(h0[4], h0[5]), pack2(h0[6], h0[7]));
    *(uint4*)(o1 + o) = make_uint4(pack2(h1[0], h1[1]), pack2(h1[2], h1[3]),
                                   pack2(h1[4], h1[5]), pack2(h1[6], h1[7]));
}

// ============================ chunk prefetch ============================
template <int DIN, int NPASS, int NTHR>
__device__ __forceinline__ void issue_chunk(
    uint32_t smb, int buf, int64_t r0, int n0, int k0,
    const __half* __restrict__ a0, const __half* __restrict__ a1,
    const __half* w0, const __half* w1, int tid) {
    constexpr int BUFB  = 2 * ATILE + 2 * NPASS * 128;
    constexpr int WTILE = NPASS * 128;
    const uint32_t base = smb + buf * BUFB;
    const __half* ap[2] = {a0, a1};
    const __half* wp[2] = {w0, w1};
#pragma unroll
    for (int s = 0; s < 2; s++) {
        constexpr int ITA = TM * 8 / NTHR;        // 2 (512 thr) / 4 (256 thr)
#pragma unroll
        for (int it = 0; it < ITA; it++) {
            int i = tid + it * NTHR;
            int r = i >> 3, q = i & 7;
            const void* src = ap[s] + (r0 + r) * (int64_t)DIN + k0 + q * 8;
            uint32_t dst = base + s * ATILE + swz((uint32_t)(r * 128 + q * 16));
            CP_ASYNC16(dst, src);
        }
    }
#pragma unroll
    for (int t = 0; t < 2; t++) {
        constexpr int ITW = NPASS * 8 / NTHR;     // 4 / 2 / 1
#pragma unroll
        for (int it = 0; it < ITW; it++) {
            int i = tid + it * NTHR;
            int r = i >> 3, q = i & 7;
            const void* src = wp[t] + (n0 + r) * (int64_t)DIN + k0 + q * 8;
            uint32_t dst = base + 2 * ATILE + t * WTILE +
                           swz((uint32_t)(r * 128 + q * 16));
            CP_ASYNC16(dst, src);
        }
    }
}

// ============================ layer kernel ============================
// OMODE 0: fp32 h out + LN stats + fused phase-2 LN/ReLU/split -> planes
// OMODE 1: fused LN/ReLU/split from regs (NT==1), no fp32 out
// OMODE 2: fp32 out only
template <int DIN, int DOUT, int OMODE, int NTHR>
__global__ __launch_bounds__(NTHR, 1) void layer_kernel(
    const __half* __restrict__ a0, const __half* __restrict__ a1, int w_off,
    const float* __restrict__ bias,
    const float* __restrict__ go, const float* __restrict__ bo,
    float* __restrict__ outf,
    __half* __restrict__ o0, __half* __restrict__ o1) {
    extern __shared__ char sm[];
    const uint32_t smb = smem_u32(sm);
    const int tid  = threadIdx.x;
    const int lane = tid & 31;
    const int wid  = tid >> 5;
    const int64_t r0 = (int64_t)blockIdx.x * TM;

    constexpr int NPASS = npass_of(DOUT);
    constexpr int NT    = DOUT / NPASS;
    constexpr int NWC   = (NTHR == 512) ? 4 : 2;   // col groups of warps
    constexpr int WC    = NPASS / NWC;
    constexpr int NFRAG = WC / 8;
    constexpr int NCH   = DIN / KCH;
    constexpr int BUFB  = 2 * ATILE + 2 * NPASS * 128;
    constexpr int WTILE = NPASS * 128;
    constexpr int SM_P  = 2 * BUFB;
    static_assert(OMODE != 1 || NT == 1, "fused reg split needs NT==1");
    static_assert(NFRAG >= 2, "need at least 2 fragments per warp");

    const int wr  = wid / NWC;            // 0..3 (32-row group)
    const int wc  = wid % NWC;
    const int R0  = wr * 32;
    const int C0w = wc * WC;

    const int sub  = lane >> 3;
    const int arow = (sub & 1) * 8 + (lane & 7);
    const int acol = (sub >> 1) * 8;
    const int brow = (sub >> 1) * 8 + (lane & 7);
    const int bcol = (sub & 1) * 8;

    float* bias_s = (float*)(sm + SM_P);
    float* go_s   = (float*)(sm + SM_P + 2048);
    float* bo_s   = (float*)(sm + SM_P + 4096);
    float* s1_s   = (float*)(sm + SM_P + 6144);
    float* s2_s   = (float*)(sm + SM_P + 6656);

    for (int i = tid; i < DOUT; i += NTHR) bias_s[i] = bias[i];
    if (OMODE != 2)
        for (int i = tid; i < DOUT; i += NTHR) {
            go_s[i] = go[i];
            bo_s[i] = bo[i];
        }
    if (OMODE != 2 && tid < TM) {
        s1_s[tid] = 0.f;
        s2_s[tid] = 0.f;
    }
    __syncthreads();

    const __half* w0 = g_w0 + w_off;
    const __half* w1 = g_w1 + w_off;

    float acc[2][NFRAG][4];

    for (int nt = 0; nt < NT; nt++) {
#pragma unroll
        for (int i = 0; i < 2; i++)
#pragma unroll
            for (int j = 0; j < NFRAG; j++)
#pragma unroll
                for (int q = 0; q < 4; q++) acc[i][j][q] = 0.f;

        const int n0 = nt * NPASS;
        issue_chunk<DIN, NPASS, NTHR>(smb, 0, r0, n0, 0, a0, a1, w0, w1, tid);
        CP_ASYNC_COMMIT();

        for (int ch = 0; ch < NCH; ch++) {
            if (ch + 1 < NCH) {
                issue_chunk<DIN, NPASS, NTHR>(smb, (ch + 1) & 1, r0, n0,
                                              (ch + 1) * KCH, a0, a1, w0, w1,
                                              tid);
                CP_ASYNC_COMMIT();
                CP_ASYNC_WAIT1();
            } else {
                CP_ASYNC_WAIT0();
            }
            __syncthreads();

            const uint32_t base = smb + (ch & 1) * BUFB;
#pragma unroll
            for (int kk = 0; kk < KCH; kk += 16) {
                uint32_t af[2][2][4];
#pragma unroll
                for (int s = 0; s < 2; s++)
#pragma unroll
                    for (int i = 0; i < 2; i++) {
                        uint32_t off = (uint32_t)((R0 + i * 16 + arow) * 128 +
                                                  (kk + acol) * 2);
                        LDSM4(af[s][i], base + s * ATILE + swz(off));
                    }
#pragma unroll
                for (int j2 = 0; j2 < NFRAG / 2; j2++) {
                    uint32_t bfm[2][4];
#pragma unroll
                    for (int t = 0; t < 2; t++) {
                        uint32_t off = (uint32_t)((C0w + j2 * 16 + brow) * 128 +
                                                  (kk + bcol) * 2);
                        LDSM4(bfm[t], base + 2 * ATILE + t * WTILE + swz(off));
                    }
                    // 3 products: small first (h1w0, h0w1), then h0w0
                    constexpr int PS[3] = {1, 0, 0};
                    constexpr int PT[3] = {0, 1, 0};
#pragma unroll
                    for (int p = 0; p < 3; p++) {
                        const int s = PS[p], t = PT[p];
#pragma unroll
                        for (int i = 0; i < 2; i++) {
                            MMAF16(acc[i][2 * j2],     af[s][i],
                                   bfm[t][0], bfm[t][1]);
                            MMAF16(acc[i][2 * j2 + 1], af[s][i],
                                   bfm[t][2], bfm[t][3]);
                        }
                    }
                }
            }
            __syncthreads();
        }

        // ---- per-pass epilogue: bias, fp32 store, stats ----
#pragma unroll
        for (int i = 0; i < 2; i++) {
            const int rla = R0 + i * 16 + (lane >> 2);
            float s1a = 0.f, s2a = 0.f, s1b = 0.f, s2b = 0.f;
#pragma unroll
            for (int j = 0; j < NFRAG; j++) {
                int cg = n0 + C0w + j * 8 + (lane & 3) * 2;
                acc[i][j][0] += bias_s[cg];
                acc[i][j][1] += bias_s[cg + 1];
                acc[i][j][2] += bias_s[cg];
                acc[i][j][3] += bias_s[cg + 1];
                if (OMODE != 1) {
                    *(float2*)(outf + (r0 + rla) * (int64_t)DOUT + cg) =
                        make_float2(acc[i][j][0], acc[i][j][1]);
                    *(float2*)(outf + (r0 + rla + 8) * (int64_t)DOUT + cg) =
                        make_float2(acc[i][j][2], acc[i][j][3]);
                }
                if (OMODE != 2) {
                    s1a += acc[i][j][0] + acc[i][j][1];
                    s2a += fmaf(acc[i][j][0], acc[i][j][0],
                                acc[i][j][1] * acc[i][j][1]);
                    s1b += acc[i][j][2] + acc[i][j][3];
                    s2b += fmaf(acc[i][j][2], acc[i][j][2],
                                acc[i][j][3] * acc[i][j][3]);
                }
            }
            if (OMODE != 2) {
#pragma unroll
                for (int o = 1; o <= 2; o <<= 1) {
                    s1a += __shfl_xor_sync(0xffffffffu, s1a, o);
                    s2a += __shfl_xor_sync(0xffffffffu, s2a, o);
                    s1b += __shfl_xor_sync(0xffffffffu, s1b, o);
                    s2b += __shfl_xor_sync(0xffffffffu, s2b, o);
                }
                if ((lane & 3) == 0) {
                    atomicAdd(&s1_s[rla], s1a);
                    atomicAdd(&s2_s[rla], s2a);
                    atomicAdd(&s1_s[rla + 8], s1b);
                    atomicAdd(&s2_s[rla + 8], s2b);
                }
            }
        }
    }

    if (OMODE != 2) {
        __syncthreads();
        if (tid < TM) {
            float mu  = s1_s[tid] * (1.0f / DOUT);
            float var = s2_s[tid] * (1.0f / DOUT) - mu * mu;
            s1_s[tid] = mu;
            s2_s[tid] = rsqrtf(var + LN_EPS);
        }
        __syncthreads();
    }

    if (OMODE == 0) {
        // phase-2: re-read own fp32 h tile (L2-hot), LN+ReLU+split -> planes
        constexpr int QF = NTHR / TM;               // col quarters per row
        const int row = tid / QF;
        const int cb  = (tid % QF) * (DOUT / QF);
        const float mu = s1_s[row], rs = s2_s[row];
        const float* src = outf + (r0 + row) * (int64_t)DOUT + cb;
        const int64_t od = (r0 + row) * (int64_t)DOUT + cb;
#pragma unroll 2
        for (int c = 0; c < DOUT / QF; c += 8) {
            float4 v0 = *(const float4*)(src + c);
            float4 v1 = *(const float4*)(src + c + 4);
            float x[8] = {v0.x, v0.y, v0.z, v0.w, v1.x, v1.y, v1.z, v1.w};
            __half h0[8], h1[8];
#pragma unroll
            for (int j = 0; j < 8; j++) {
                int cc = cb + c + j;
                float y = fmaxf((x[j] - mu) * rs * go_s[cc] + bo_s[cc], 0.f);
                split2(y, h0[j], h1[j]);
            }
            *(uint4*)(o0 + od + c) =
                make_uint4(pack2(h0[0], h0[1]), pack2(h0[2], h0[3]),
                           pack2(h0[4], h0[5]), pack2(h0[6], h0[7]));
            *(uint4*)(o1 + od + c) =
                make_uint4(pack2(h1[0], h1[1]), pack2(h1[2], h1[3]),
                           pack2(h1[4], h1[5]), pack2(h1[6], h1[7]));
        }
    }

    if (OMODE == 1) {
#pragma unroll
        for (int i = 0; i < 2; i++) {
            const int rla = R0 + i * 16 + (lane >> 2);
            float muA = s1_s[rla], rsA = s2_s[rla];
            float muB = s1_s[rla + 8], rsB = s2_s[rla + 8];
#pragma unroll
            for (int j = 0; j < NFRAG; j++) {
                int cg = C0w + j * 8 + (lane & 3) * 2;
                float ga = go_s[cg], gb = go_s[cg + 1];
                float ba = bo_s[cg], bb = bo_s[cg + 1];
                float v0 = fmaxf((acc[i][j][0] - muA) * rsA * ga + ba, 0.f);
                float v1 = fmaxf((acc[i][j][1] - muA) * rsA * gb + bb, 0.f);
                float v2 = fmaxf((acc[i][j][2] - muB) * rsB * ga + ba, 0.f);
                float v3 = fmaxf((acc[i][j][3] - muB) * rsB * gb + bb, 0.f);
                __half p0[2], p1[2], p2[2], p3[2];
                split2(v0, p0[0], p0[1]);
                split2(v1, p1[0], p1[1]);
                split2(v2, p2[0], p2[1]);
                split2(v3, p3[0], p3[1]);
                int64_t oa = (r0 + rla) * (int64_t)DOUT + cg;
                int64_t ob = (r0 + rla + 8) * (int64_t)DOUT + cg;
                *(uint32_t*)(o0 + oa) = pack2(p0[0], p1[0]);
                *(uint32_t*)(o1 + oa) = pack2(p0[1], p1[1]);
                *(uint32_t*)(o0 + ob) = pack2(p2[0], p3[0]);
                *(uint32_t*)(o1 + ob) = pack2(p2[1], p3[1]);
            }
        }
    }
}

// ============================ prototypes ============================
__global__ void zero_proto_kernel() {
    int t = blockIdx.x * blockDim.x + threadIdx.x;
    if (t < 64 * 32) g_psum[t] = 0.f;
    if (t < 64) g_pcnt[t] = 0.f;
}

__global__ void proto_accum_kernel(const int* __restrict__ labels,
                                   const float* __restrict__ zs) {
    __shared__ float ssum[64 * 32];
    __shared__ float scnt[64];
    int tid = threadIdx.x, lane = tid & 31, warp = tid >> 5;
    for (int t = tid; t < 64 * 32; t += 256) ssum[t] = 0.f;
    if (tid < 64) scnt[tid] = 0.f;
    __syncthreads();
    int rbase = blockIdx.x * 512;
    for (int r = rbase + warp; r < rbase + 512; r += 8) {
        int lab = labels[r];
        lab = max(0, min(63, lab));
        float v = zs[(size_t)r * 32 + lane];
        atomicAdd(&ssum[lab * 32 + lane], v);
        if (lane == 0) atomicAdd(&scnt[lab], 1.f);
    }
    __syncthreads();
    for (int t = tid; t < 64 * 32; t += 256) atomicAdd(&g_psum[t], ssum[t]);
    if (tid < 64) atomicAdd(&g_pcnt[tid], scnt[tid]);
}

__global__ void proto_finalize_kernel() {
    int tid = threadIdx.x;
    for (int i = tid; i < 64 * 32; i += 256) {
        int c = i >> 5;
        g_psum[i] = g_psum[i] / fmaxf(g_pcnt[c], 1.f);
    }
}

// ============================ -cdist ============================
__global__ __launch_bounds__(256) void dist_kernel(const float* __restrict__ zq,
                                                   float* __restrict__ out) {
    __shared__ float ps[64 * 33];
    __shared__ float pn[64];
    __shared__ float qs[16 * 33];
    int tid = threadIdx.x;
    for (int i = tid; i < 64 * 32; i += 256)
        ps[(i >> 5) * 33 + (i & 31)] = g_psum[i];
    int qbase = blockIdx.x * 16;
    for (int i = tid; i < 16 * 32; i += 256) {
        int q = i >> 5, k = i & 31;
        qs[q * 33 + k] = zq[(size_t)(qbase + q) * 32 + k];
    }
    __syncthreads();
    if (tid < 64) {
        float s = 0.f;
#pragma unroll
        for (int k = 0; k < 32; k++) {
            float v = ps[tid * 33 + k];
            s += v * v;
        }
        pn[tid] = s;
    }
    __syncthreads();
    int c = tid & 63;
#pragma unroll
    for (int p = 0; p < 4; p++) {
        int q = p * 4 + (tid >> 6);
        float dot = 0.f, qn = 0.f;
#pragma unroll
        for (int k = 0; k < 32; k++) {
            float a = qs[q * 33 + k];
            float b = ps[c * 33 + k];
            dot = fmaf(a, b, dot);
            qn  = fmaf(a, a, qn);
        }
        float sq = qn + pn[c] - 2.f * dot;
        out[(size_t)(qbase + q) * 64 + c] = -sqrtf(fmaxf(sq, 0.f));
    }
}

// ============================ launch ============================
extern "C" void kernel_launch(void* const* d_in, const int* in_sizes, int n_in,
                              void* d_out, int out_size) {
    const float* sup = (const float*)d_in[0];
    const int*   lab = (const int*)d_in[1];
    const float* qry = (const float*)d_in[2];
    const float* W1 = (const float*)d_in[3];
    const float* b1 = (const float*)d_in[4];
    const float* g1 = (const float*)d_in[5];
    const float* be1 = (const float*)d_in[6];
    const float* W2 = (const float*)d_in[7];
    const float* b2 = (const float*)d_in[8];
    const float* g2 = (const float*)d_in[9];
    const float* be2 = (const float*)d_in[10];
    const float* W3 = (const float*)d_in[11];
    const float* b3 = (const float*)d_in[12];
    const float* g3 = (const float*)d_in[13];
    const float* be3 = (const float*)d_in[14];
    const float* W4 = (const float*)d_in[15];
    const float* b4 = (const float*)d_in[16];

    cudaFuncSetAttribute(layer_kernel<768, 512, 0, 512>,
                         cudaFuncAttributeMaxDynamicSharedMemorySize,
                         smem_of(512));
    cudaFuncSetAttribute(layer_kernel<512, 512, 0, 512>,
                         cudaFuncAttributeMaxDynamicSharedMemorySize,
                         smem_of(512));
    cudaFuncSetAttribute(layer_kernel<512, 128, 1, 512>,
                         cudaFuncAttributeMaxDynamicSharedMemorySize,
                         smem_of(128));
    cudaFuncSetAttribute(layer_kernel<128, 32, 2, 256>,
                         cudaFuncAttributeMaxDynamicSharedMemorySize,
                         smem_of(32));

    float* h = nullptr;
    __half *a0, *a1, *c0, *c1, *p0, *p1;
    cudaGetSymbolAddress((void**)&h, g_h);
    cudaGetSymbolAddress((void**)&a0, g_a0);
    cudaGetSymbolAddress((void**)&a1, g_a1);
    cudaGetSymbolAddress((void**)&c0, g_c0);
    cudaGetSymbolAddress((void**)&c1, g_c1);
    cudaGetSymbolAddress((void**)&p0, g_p0);
    cudaGetSymbolAddress((void**)&p1, g_p1);

    // 1: weight split
    split_w_all<<<(724992 + 255) / 256, 256>>>(W1, W2, W3, W4);
    // 2-3: input converts (din=768)
    convert_in<<<12288, 256>>>(sup, a0, a1, 32768 * 96);
    convert_in<<<24576, 256>>>(qry, a0 + (int64_t)32768 * 768,
                               a1 + (int64_t)32768 * 768, 65536 * 96);
    // 4: L1 -> h + planes c (LN1+ReLU fused)   [profiled slot]
    layer_kernel<768, 512, 0, 512><<<768, 512, smem_of(512)>>>(
        a0, a1, 0, b1, g1, be1, h, c0, c1);
    // 5: L2 -> h + planes a (LN2+ReLU fused)
    layer_kernel<512, 512, 0, 512><<<768, 512, smem_of(512)>>>(
        c0, c1, 393216, b2, g2, be2, h, a0, a1);
    // 6: L3 -> planes p (LN3+ReLU fused from regs)
    layer_kernel<512, 128, 1, 512><<<768, 512, smem_of(128)>>>(
        a0, a1, 655360, b3, g3, be3, nullptr, p0, p1);
    // 7: L4 -> z fp32 (stride 32)
    layer_kernel<128, 32, 2, 256><<<768, 256, smem_of(32)>>>(
        p0, p1, 720896, b4, nullptr, nullptr, h, nullptr, nullptr);
    // 8+: prototypes + distances
    zero_proto_kernel<<<8, 256>>>();
    proto_accum_kernel<<<64, 256>>>(lab, h);
    proto_finalize_kernel<<<1, 256>>>();
    dist_kernel<<<65536 / 16, 256>>>(h + (size_t)32768 * 32, (float*)d_out);
}

// round 12
// speedup vs baseline: 1.0872x; 1.0872x over previous
#include <cuda_runtime.h>
#include <cuda_fp16.h>
#include <cstdint>

#define LN_EPS 1e-5f

// ============================ PTX helpers ============================
__device__ __forceinline__ uint32_t smem_u32(const void* p) {
    uint32_t a;
    asm("{ .reg .u64 t; cvta.to.shared.u64 t, %1; cvt.u32.u64 %0, t; }"
        : "=r"(a) : "l"(p));
    return a;
}

// SW64 swizzle for 64-byte rows: XOR 16B-unit index bits[5:4] with row bits.
// 8 consecutive 64B rows -> 8 distinct 16B offsets mod 128: ldmatrix clean.
__device__ __forceinline__ uint32_t swz64(uint32_t off) {
    return off ^ ((off >> 3) & 0x30);
}

#define LDSM4(r, addr)                                                        \
    asm volatile(                                                             \
        "ldmatrix.sync.aligned.m8n8.x4.shared.b16 {%0,%1,%2,%3}, [%4];"       \
        : "=r"((r)[0]), "=r"((r)[1]), "=r"((r)[2]), "=r"((r)[3])              \
        : "r"(addr))

#define MMAF16(d, a, b0, b1)                                                  \
    asm volatile(                                                             \
        "mma.sync.aligned.m16n8k16.row.col.f32.f16.f16.f32 "                  \
        "{%0,%1,%2,%3}, {%4,%5,%6,%7}, {%8,%9}, {%0,%1,%2,%3};"               \
        : "+f"((d)[0]), "+f"((d)[1]), "+f"((d)[2]), "+f"((d)[3])              \
        : "r"((a)[0]), "r"((a)[1]), "r"((a)[2]), "r"((a)[3]),                 \
          "r"(b0), "r"(b1))

#define CP_ASYNC16(dst, src)                                                  \
    asm volatile("cp.async.cg.shared.global [%0], [%1], 16;"                  \
                 :: "r"(dst), "l"(src))
#define CP_ASYNC_COMMIT() asm volatile("cp.async.commit_group;" ::: "memory")
#define CP_ASYNC_WAIT1()  asm volatile("cp.async.wait_group 1;" ::: "memory")
#define CP_ASYNC_WAIT0()  asm volatile("cp.async.wait_group 0;" ::: "memory")

// ============================ geometry ============================
constexpr int TM    = 128;
constexpr int KCH   = 32;                 // 64 B rows (fp16)
constexpr int ATILE = TM * KCH * 2;       // 8192 B per A limb tile

__host__ __device__ constexpr int npass_of(int dout) {
    return dout > 128 ? 128 : dout;
}
__host__ __device__ constexpr int bufb_of(int dout) {
    return 2 * ATILE + 2 * npass_of(dout) * KCH * 2;
}
__host__ __device__ constexpr int smem_of(int dout) {
    return 2 * bufb_of(dout) + 7168;
}

// ============================ scratch ============================
__device__ __align__(256) float  g_h[98304ull * 512];
__device__ __align__(256) __half g_a0[98304ull * 768];
__device__ __align__(256) __half g_a1[98304ull * 768];
__device__ __align__(256) __half g_c0[98304ull * 512];
__device__ __align__(256) __half g_c1[98304ull * 512];
__device__ __align__(256) __half g_p0[98304ull * 128];
__device__ __align__(256) __half g_p1[98304ull * 128];
__device__ __align__(256) __half g_w0[724992];
__device__ __align__(256) __half g_w1[724992];
__device__ float g_psum[64 * 32];
__device__ float g_pcnt[64];

// ============================ 2-way fp16 split ============================
__device__ __forceinline__ void split2(float a, __half& h0, __half& h1) {
    h0 = __float2half_rn(a);
    h1 = __float2half_rn(a - __half2float(h0));
}
__device__ __forceinline__ uint32_t pack2(__half a, __half b) {
    return ((uint32_t)__half_as_ushort(b) << 16) | (uint32_t)__half_as_ushort(a);
}

// ============================ W prep ============================
__global__ void split_w_all(const float* __restrict__ W1,
                            const float* __restrict__ W2,
                            const float* __restrict__ W3,
                            const float* __restrict__ W4) {
    int i = blockIdx.x * 256 + threadIdx.x;
    if (i >= 724992) return;
    float v;
    if (i < 393216) v = W1[i];
    else if (i < 655360) v = W2[i - 393216];
    else if (i < 720896) v = W3[i - 655360];
    else v = W4[i - 720896];
    __half h0, h1;
    split2(v, h0, h1);
    g_w0[i] = h0;
    g_w1[i] = h1;
}

// ============================ input convert ============================
__global__ __launch_bounds__(256) void convert_in(
    const float* __restrict__ x, __half* __restrict__ o0,
    __half* __restrict__ o1, int total8) {
    int i = blockIdx.x * 256 + threadIdx.x;
    if (i >= total8) return;
    int r = i / 96;
    int q = i - r * 96;
    const float* src = x + (int64_t)r * 768 + q * 8;
    float4 v0 = *(const float4*)src;
    float4 v1 = *(const float4*)(src + 4);
    float xx[8] = {v0.x, v0.y, v0.z, v0.w, v1.x, v1.y, v1.z, v1.w};
    __half h0[8], h1[8];
#pragma unroll
    for (int j = 0; j < 8; j++) split2(xx[j], h0[j], h1[j]);
    int64_t o = (int64_t)r * 768 + q * 8;
    *(uint4*)(o0 + o) = make_uint4(pack2(h0[0], h0[1]), pack2(h0[2], h0[3]),
                                   pack2(h0[4], h0[5]), pack2(h0[6], h0[7]));
    *(uint4*)(o1 + o) = make_uint4(pack2(h1[0], h1[1]), pack2(h1[2], h1[3]),
                                   pack2(h1[4], h1[5]), pack2(h1[6], h1[7]));
}

// ============================ chunk prefetch ============================
// A: [128 x 32] per limb (64B rows, 4 quads); W: [NPASS x 32] per limb.
template <int DIN, int NPASS>
__device__ __forceinline__ void issue_chunk(
    uint32_t smb, int buf, int64_t r0, int n0, int k0,
    const __half* __restrict__ a0, const __half* __restrict__ a1,
    const __half* w0, const __half* w1, int tid) {
    constexpr int BUFB  = 2 * ATILE + 2 * NPASS * 64;
    constexpr int WTILE = NPASS * 64;
    const uint32_t base = smb + buf * BUFB;
    const __half* ap[2] = {a0, a1};
    const __half* wp[2] = {w0, w1};
#pragma unroll
    for (int s = 0; s < 2; s++) {
#pragma unroll
        for (int it = 0; it < 2; it++) {          // 128 rows * 4 quads / 256
            int i = tid + it * 256;
            int r = i >> 2, q = i & 3;
            const void* src = ap[s] + (r0 + r) * (int64_t)DIN + k0 + q * 8;
            uint32_t dst = base + s * ATILE + swz64((uint32_t)(r * 64 + q * 16));
            CP_ASYNC16(dst, src);
        }
    }
#pragma unroll
    for (int t = 0; t < 2; t++) {
        for (int i = tid; i < NPASS * 4; i += 256) {
            int r = i >> 2, q = i & 3;
            const void* src = wp[t] + (n0 + r) * (int64_t)DIN + k0 + q * 8;
            uint32_t dst = base + 2 * ATILE + t * WTILE +
                           swz64((uint32_t)(r * 64 + q * 16));
            CP_ASYNC16(dst, src);
        }
    }
}

// ============================ layer kernel ============================
// OMODE 0: fp32 h out + LN stats + fused phase-2 LN/ReLU/split -> planes
// OMODE 1: fused LN/ReLU/split from regs (NT==1), no fp32 out
// OMODE 2: fp32 out only
// 256 threads, 2 CTAs/SM (the occupancy fix for the 48%-tensor profile).
template <int DIN, int DOUT, int OMODE>
__global__ __launch_bounds__(256, 2) void layer_kernel(
    const __half* __restrict__ a0, const __half* __restrict__ a1, int w_off,
    const float* __restrict__ bias,
    const float* __restrict__ go, const float* __restrict__ bo,
    float* __restrict__ outf,
    __half* __restrict__ o0, __half* __restrict__ o1) {
    extern __shared__ char sm[];
    const uint32_t smb = smem_u32(sm);
    const int tid  = threadIdx.x;
    const int lane = tid & 31;
    const int wid  = tid >> 5;
    const int64_t r0 = (int64_t)blockIdx.x * TM;

    constexpr int NPASS = npass_of(DOUT);
    constexpr int NT    = DOUT / NPASS;
    constexpr int WC    = NPASS / 2;       // 2 col groups of warps
    constexpr int NFRAG = WC / 8;          // 8 / 2
    constexpr int NCH   = DIN / KCH;
    constexpr int BUFB  = 2 * ATILE + 2 * NPASS * 64;
    constexpr int WTILE = NPASS * 64;
    constexpr int SM_P  = 2 * BUFB;
    static_assert(OMODE != 1 || NT == 1, "fused reg split needs NT==1");
    static_assert(NFRAG >= 2, "need at least 2 fragments per warp");

    const int wr  = wid >> 1;              // 0..3 (32-row group)
    const int wc  = wid & 1;
    const int R0  = wr * 32;
    const int C0w = wc * WC;

    const int sub  = lane >> 3;
    const int arow = (sub & 1) * 8 + (lane & 7);
    const int acol = (sub >> 1) * 8;
    const int brow = (sub >> 1) * 8 + (lane & 7);
    const int bcol = (sub & 1) * 8;

    float* bias_s = (float*)(sm + SM_P);
    float* go_s   = (float*)(sm + SM_P + 2048);
    float* bo_s   = (float*)(sm + SM_P + 4096);
    float* s1_s   = (float*)(sm + SM_P + 6144);
    float* s2_s   = (float*)(sm + SM_P + 6656);

    for (int i = tid; i < DOUT; i += 256) bias_s[i] = bias[i];
    if (OMODE != 2)
        for (int i = tid; i < DOUT; i += 256) {
            go_s[i] = go[i];
            bo_s[i] = bo[i];
        }
    if (OMODE != 2 && tid < TM) {
        s1_s[tid] = 0.f;
        s2_s[tid] = 0.f;
    }
    __syncthreads();

    const __half* w0 = g_w0 + w_off;
    const __half* w1 = g_w1 + w_off;

    float acc[2][NFRAG][4];

    for (int nt = 0; nt < NT; nt++) {
#pragma unroll
        for (int i = 0; i < 2; i++)
#pragma unroll
            for (int j = 0; j < NFRAG; j++)
#pragma unroll
                for (int q = 0; q < 4; q++) acc[i][j][q] = 0.f;

        const int n0 = nt * NPASS;
        issue_chunk<DIN, NPASS>(smb, 0, r0, n0, 0, a0, a1, w0, w1, tid);
        CP_ASYNC_COMMIT();

        for (int ch = 0; ch < NCH; ch++) {
            if (ch + 1 < NCH) {
                issue_chunk<DIN, NPASS>(smb, (ch + 1) & 1, r0, n0,
                                        (ch + 1) * KCH, a0, a1, w0, w1, tid);
                CP_ASYNC_COMMIT();
                CP_ASYNC_WAIT1();
            } else {
                CP_ASYNC_WAIT0();
            }
            __syncthreads();

            const uint32_t base = smb + (ch & 1) * BUFB;
#pragma unroll
            for (int kk = 0; kk < KCH; kk += 16) {
                uint32_t af[2][2][4];
#pragma unroll
                for (int s = 0; s < 2; s++)
#pragma unroll
                    for (int i = 0; i < 2; i++) {
                        uint32_t off = (uint32_t)((R0 + i * 16 + arow) * 64 +
                                                  (kk + acol) * 2);
                        LDSM4(af[s][i], base + s * ATILE + swz64(off));
                    }
#pragma unroll
                for (int j2 = 0; j2 < NFRAG / 2; j2++) {
                    uint32_t bfm[2][4];
#pragma unroll
                    for (int t = 0; t < 2; t++) {
                        uint32_t off = (uint32_t)((C0w + j2 * 16 + brow) * 64 +
                                                  (kk + bcol) * 2);
                        LDSM4(bfm[t], base + 2 * ATILE + t * WTILE + swz64(off));
                    }
                    // 3 products: small first (h1w0, h0w1), then h0w0
                    constexpr int PS[3] = {1, 0, 0};
                    constexpr int PT[3] = {0, 1, 0};
#pragma unroll
                    for (int p = 0; p < 3; p++) {
                        const int s = PS[p], t = PT[p];
#pragma unroll
                        for (int i = 0; i < 2; i++) {
                            MMAF16(acc[i][2 * j2],     af[s][i],
                                   bfm[t][0], bfm[t][1]);
                            MMAF16(acc[i][2 * j2 + 1], af[s][i],
                                   bfm[t][2], bfm[t][3]);
                        }
                    }
                }
            }
            __syncthreads();
        }

        // ---- per-pass epilogue: bias, fp32 store, stats ----
#pragma unroll
        for (int i = 0; i < 2; i++) {
            const int rla = R0 + i * 16 + (lane >> 2);
            float s1a = 0.f, s2a = 0.f, s1b = 0.f, s2b = 0.f;
#pragma unroll
            for (int j = 0; j < NFRAG; j++) {
                int cg = n0 + C0w + j * 8 + (lane & 3) * 2;
                acc[i][j][0] += bias_s[cg];
                acc[i][j][1] += bias_s[cg + 1];
                acc[i][j][2] += bias_s[cg];
                acc[i][j][3] += bias_s[cg + 1];
                if (OMODE != 1) {
                    *(float2*)(outf + (r0 + rla) * (int64_t)DOUT + cg) =
                        make_float2(acc[i][j][0], acc[i][j][1]);
                    *(float2*)(outf + (r0 + rla + 8) * (int64_t)DOUT + cg) =
                        make_float2(acc[i][j][2], acc[i][j][3]);
                }
                if (OMODE != 2) {
                    s1a += acc[i][j][0] + acc[i][j][1];
                    s2a += fmaf(acc[i][j][0], acc[i][j][0],
                                acc[i][j][1] * acc[i][j][1]);
                    s1b += acc[i][j][2] + acc[i][j][3];
                    s2b += fmaf(acc[i][j][2], acc[i][j][2],
                                acc[i][j][3] * acc[i][j][3]);
                }
            }
            if (OMODE != 2) {
#pragma unroll
                for (int o = 1; o <= 2; o <<= 1) {
                    s1a += __shfl_xor_sync(0xffffffffu, s1a, o);
                    s2a += __shfl_xor_sync(0xffffffffu, s2a, o);
                    s1b += __shfl_xor_sync(0xffffffffu, s1b, o);
                    s2b += __shfl_xor_sync(0xffffffffu, s2b, o);
                }
                if ((lane & 3) == 0) {
                    atomicAdd(&s1_s[rla], s1a);
                    atomicAdd(&s2_s[rla], s2a);
                    atomicAdd(&s1_s[rla + 8], s1b);
                    atomicAdd(&s2_s[rla + 8], s2b);
                }
            }
        }
    }

    if (OMODE != 2) {
        __syncthreads();
        if (tid < TM) {
            float mu  = s1_s[tid] * (1.0f / DOUT);
            float var = s2_s[tid] * (1.0f / DOUT) - mu * mu;
            s1_s[tid] = mu;
            s2_s[tid] = rsqrtf(var + LN_EPS);
        }
        __syncthreads();
    }

    if (OMODE == 0) {
        // phase-2: re-read own fp32 h tile (L2-hot), LN+ReLU+split -> planes
        const int row = tid >> 1;
        const int cb  = (tid & 1) * (DOUT / 2);
        const float mu = s1_s[row], rs = s2_s[row];
        const float* src = outf + (r0 + row) * (int64_t)DOUT + cb;
        const int64_t od = (r0 + row) * (int64_t)DOUT + cb;
#pragma unroll 2
        for (int c = 0; c < DOUT / 2; c += 8) {
            float4 v0 = *(const float4*)(src + c);
            float4 v1 = *(const float4*)(src + c + 4);
            float x[8] = {v0.x, v0.y, v0.z, v0.w, v1.x, v1.y, v1.z, v1.w};
            __half h0[8], h1[8];
#pragma unroll
            for (int j = 0; j < 8; j++) {
                int cc = cb + c + j;
                float y = fmaxf((x[j] - mu) * rs * go_s[cc] + bo_s[cc], 0.f);
                split2(y, h0[j], h1[j]);
            }
            *(uint4*)(o0 + od + c) =
                make_uint4(pack2(h0[0], h0[1]), pack2(h0[2], h0[3]),
                           pack2(h0[4], h0[5]), pack2(h0[6], h0[7]));
            *(uint4*)(o1 + od + c) =
                make_uint4(pack2(h1[0], h1[1]), pack2(h1[2], h1[3]),
                           pack2(h1[4], h1[5]), pack2(h1[6], h1[7]));
        }
    }

    if (OMODE == 1) {
#pragma unroll
        for (int i = 0; i < 2; i++) {
            const int rla = R0 + i * 16 + (lane >> 2);
            float muA = s1_s[rla], rsA = s2_s[rla];
            float muB = s1_s[rla + 8], rsB = s2_s[rla + 8];
#pragma unroll
            for (int j = 0; j < NFRAG; j++) {
                int cg = C0w + j * 8 + (lane & 3) * 2;
                float ga = go_s[cg], gb = go_s[cg + 1];
                float ba = bo_s[cg], bb = bo_s[cg + 1];
                float v0 = fmaxf((acc[i][j][0] - muA) * rsA * ga + ba, 0.f);
                float v1 = fmaxf((acc[i][j][1] - muA) * rsA * gb + bb, 0.f);
                float v2 = fmaxf((acc[i][j][2] - muB) * rsB * ga + ba, 0.f);
                float v3 = fmaxf((acc[i][j][3] - muB) * rsB * gb + bb, 0.f);
                __half p0[2], p1[2], p2[2], p3[2];
                split2(v0, p0[0], p0[1]);
                split2(v1, p1[0], p1[1]);
                split2(v2, p2[0], p2[1]);
                split2(v3, p3[0], p3[1]);
                int64_t oa = (r0 + rla) * (int64_t)DOUT + cg;
                int64_t ob = (r0 + rla + 8) * (int64_t)DOUT + cg;
                *(uint32_t*)(o0 + oa) = pack2(p0[0], p1[0]);
                *(uint32_t*)(o1 + oa) = pack2(p0[1], p1[1]);
                *(uint32_t*)(o0 + ob) = pack2(p2[0], p3[0]);
                *(uint32_t*)(o1 + ob) = pack2(p2[1], p3[1]);
            }
        }
    }
}

// ============================ prototypes ============================
__global__ void zero_proto_kernel() {
    int t = blockIdx.x * blockDim.x + threadIdx.x;
    if (t < 64 * 32) g_psum[t] = 0.f;
    if (t < 64) g_pcnt[t] = 0.f;
}

__global__ void proto_accum_kernel(const int* __restrict__ labels,
                                   const float* __restrict__ zs) {
    __shared__ float ssum[64 * 32];
    __shared__ float scnt[64];
    int tid = threadIdx.x, lane = tid & 31, warp = tid >> 5;
    for (int t = tid; t < 64 * 32; t += 256) ssum[t] = 0.f;
    if (tid < 64) scnt[tid] = 0.f;
    __syncthreads();
    int rbase = blockIdx.x * 512;
    for (int r = rbase + warp; r < rbase + 512; r += 8) {
        int lab = labels[r];
        lab = max(0, min(63, lab));
        float v = zs[(size_t)r * 32 + lane];
        atomicAdd(&ssum[lab * 32 + lane], v);
        if (lane == 0) atomicAdd(&scnt[lab], 1.f);
    }
    __syncthreads();
    for (int t = tid; t < 64 * 32; t += 256) atomicAdd(&g_psum[t], ssum[t]);
    if (tid < 64) atomicAdd(&g_pcnt[tid], scnt[tid]);
}

__global__ void proto_finalize_kernel() {
    int tid = threadIdx.x;
    for (int i = tid; i < 64 * 32; i += 256) {
        int c = i >> 5;
        g_psum[i] = g_psum[i] / fmaxf(g_pcnt[c], 1.f);
    }
}

// ============================ -cdist ============================
__global__ __launch_bounds__(256) void dist_kernel(const float* __restrict__ zq,
                                                   float* __restrict__ out) {
    __shared__ float ps[64 * 33];
    __shared__ float pn[64];
    __shared__ float qs[16 * 33];
    int tid = threadIdx.x;
    for (int i = tid; i < 64 * 32; i += 256)
        ps[(i >> 5) * 33 + (i & 31)] = g_psum[i];
    int qbase = blockIdx.x * 16;
    for (int i = tid; i < 16 * 32; i += 256) {
        int q = i >> 5, k = i & 31;
        qs[q * 33 + k] = zq[(size_t)(qbase + q) * 32 + k];
    }
    __syncthreads();
    if (tid < 64) {
        float s = 0.f;
#pragma unroll
        for (int k = 0; k < 32; k++) {
            float v = ps[tid * 33 + k];
            s += v * v;
        }
        pn[tid] = s;
    }
    __syncthreads();
    int c = tid & 63;
#pragma unroll
    for (int p = 0; p < 4; p++) {
        int q = p * 4 + (tid >> 6);
        float dot = 0.f, qn = 0.f;
#pragma unroll
        for (int k = 0; k < 32; k++) {
            float a = qs[q * 33 + k];
            float b = ps[c * 33 + k];
            dot = fmaf(a, b, dot);
            qn  = fmaf(a, a, qn);
        }
        float sq = qn + pn[c] - 2.f * dot;
        out[(size_t)(qbase + q) * 64 + c] = -sqrtf(fmaxf(sq, 0.f));
    }
}

// ============================ launch ============================
extern "C" void kernel_launch(void* const* d_in, const int* in_sizes, int n_in,
                              void* d_out, int out_size) {
    const float* sup = (const float*)d_in[0];
    const int*   lab = (const int*)d_in[1];
    const float* qry = (const float*)d_in[2];
    const float* W1 = (const float*)d_in[3];
    const float* b1 = (const float*)d_in[4];
    const float* g1 = (const float*)d_in[5];
    const float* be1 = (const float*)d_in[6];
    const float* W2 = (const float*)d_in[7];
    const float* b2 = (const float*)d_in[8];
    const float* g2 = (const float*)d_in[9];
    const float* be2 = (const float*)d_in[10];
    const float* W3 = (const float*)d_in[11];
    const float* b3 = (const float*)d_in[12];
    const float* g3 = (const float*)d_in[13];
    const float* be3 = (const float*)d_in[14];
    const float* W4 = (const float*)d_in[15];
    const float* b4 = (const float*)d_in[16];

    cudaFuncSetAttribute(layer_kernel<768, 512, 0>,
                         cudaFuncAttributeMaxDynamicSharedMemorySize,
                         smem_of(512));
    cudaFuncSetAttribute(layer_kernel<512, 512, 0>,
                         cudaFuncAttributeMaxDynamicSharedMemorySize,
                         smem_of(512));
    cudaFuncSetAttribute(layer_kernel<512, 128, 1>,
                         cudaFuncAttributeMaxDynamicSharedMemorySize,
                         smem_of(128));
    cudaFuncSetAttribute(layer_kernel<128, 32, 2>,
                         cudaFuncAttributeMaxDynamicSharedMemorySize,
                         smem_of(32));

    float* h = nullptr;
    __half *a0, *a1, *c0, *c1, *p0, *p1;
    cudaGetSymbolAddress((void**)&h, g_h);
    cudaGetSymbolAddress((void**)&a0, g_a0);
    cudaGetSymbolAddress((void**)&a1, g_a1);
    cudaGetSymbolAddress((void**)&c0, g_c0);
    cudaGetSymbolAddress((void**)&c1, g_c1);
    cudaGetSymbolAddress((void**)&p0, g_p0);
    cudaGetSymbolAddress((void**)&p1, g_p1);

    // 1: weight split
    split_w_all<<<(724992 + 255) / 256, 256>>>(W1, W2, W3, W4);
    // 2-3: input converts
    convert_in<<<12288, 256>>>(sup, a0, a1, 32768 * 96);
    convert_in<<<24576, 256>>>(qry, a0 + (int64_t)32768 * 768,
                               a1 + (int64_t)32768 * 768, 65536 * 96);
    // 4: L1 -> h + planes c (LN1+ReLU fused)   [profiled slot]
    layer_kernel<768, 512, 0><<<768, 256, smem_of(512)>>>(
        a0, a1, 0, b1, g1, be1, h, c0, c1);
    // 5: L2 -> h + planes a (LN2+ReLU fused)
    layer_kernel<512, 512, 0><<<768, 256, smem_of(512)>>>(
        c0, c1, 393216, b2, g2, be2, h, a0, a1);
    // 6: L3 -> planes p (LN3+ReLU fused from regs)
    layer_kernel<512, 128, 1><<<768, 256, smem_of(128)>>>(
        a0, a1, 655360, b3, g3, be3, nullptr, p0, p1);
    // 7: L4 -> z fp32 (stride 32)
    layer_kernel<128, 32, 2><<<768, 256, smem_of(32)>>>(
        p0, p1, 720896, b4, nullptr, nullptr, h, nullptr, nullptr);
    // 8+: prototypes + distances
    zero_proto_kernel<<<8, 256>>>();
    proto_accum_kernel<<<64, 256>>>(lab, h);
    proto_finalize_kernel<<<1, 256>>>();
    dist_kernel<<<65536 / 16, 256>>>(h + (size_t)32768 * 32, (float*)d_out);
}